// round 15
// baseline (speedup 1.0000x reference)
#include <cuda_runtime.h>

// QLSTM on GB300 — R15: column-local transfer chains, one warp per batch
// element (4 circuits SIMD across lanes), zero shuffles in the chain.
//   lane = c*8 + side*4 + colIdx ; side 0: Rm column, side 1: L column.
//   Rm_new[r] = N_j[r] * sum_s g_j[r^s] Rm_old[s]      (column-local)
//   L_new[t]  = g_j[t] L_old[0] + g_j[t^3] L_old[3]    (same form, o1=o2=0)
//   g_j[m] = conj(v_j[m>>1]) v_j[m&1]  (produced directly by preact lanes)
//   E_w = Re sum L_w .* Rm_w (column dots + 2-shfl reduce), E_9 / E_0 from
//   live Rm_9 registers. No __syncthreads anywhere in the step loop.

#define TT 64
#define BB 256
#define DD 32
#define HH 10
#define NTH 32

struct Smem {
    float4 sRmS[4][8][8];       // Rm_w snapshots, w=1..8, column-major
    float4 sLS[4][8][8];        // L_w snapshots,  w=1..8, column-major
    float2 sG[4][HH][4];        // per-circuit per-wire g tables (step-dep)
    float2 sN[HH][4];           // N_j = U_j^dag Z U_j (fixed)
    float2 sKc[16];             // K column-major: sKc[c*4+t] = K[t,c]
    float4 sU0[HH];             // layer-1 gate (ax,ay,bx,by)
    float  sWx[TT][40];         // 0.5*(W.x + b) all steps
    float  sWh[4][HH][HH];      // 0.5*W_h
    float  qpart[4][HH];
};

__device__ __forceinline__ float2 cmul(float2 a, float2 b) {
    return make_float2(a.x*b.x - a.y*b.y, a.x*b.y + a.y*b.x);
}
__device__ __forceinline__ float2 cmulc(float2 a, float2 b) {   // conj(a)*b
    return make_float2(a.x*b.x + a.y*b.y, a.x*b.y - a.y*b.x);
}
__device__ __forceinline__ float2 cfma(float2 a, float2 b, float2 acc) {
    acc.x = fmaf(a.x, b.x, fmaf(-a.y, b.y, acc.x));
    acc.y = fmaf(a.x, b.y, fmaf( a.y, b.x, acc.y));
    return acc;
}
__device__ __forceinline__ float fast_tanh(float x) {
    float r;
    asm("tanh.approx.f32 %0, %1;" : "=f"(r) : "f"(x));
    return r;
}
__device__ __forceinline__ float fast_sigmoid(float x) {
    return fmaf(0.5f, fast_tanh(0.5f * x), 0.5f);
}

__global__ void __launch_bounds__(NTH, 2)
qlstm_kernel(const float* __restrict__ inputs,
             const float* __restrict__ qparams,
             const float* __restrict__ Wf, const float* __restrict__ bf,
             const float* __restrict__ Wi, const float* __restrict__ bi,
             const float* __restrict__ Wg, const float* __restrict__ bg,
             const float* __restrict__ Wo, const float* __restrict__ bo,
             float* __restrict__ out)
{
    extern __shared__ char smem_raw[];
    Smem* S = (Smem*)smem_raw;

    const int lane   = threadIdx.x;
    const int b      = blockIdx.x;
    const int c      = lane >> 3;      // circuit 0..3
    const int sub    = lane & 7;
    const int side   = sub >> 2;       // 0: Rm, 1: L
    const int colIdx = sub & 3;

    const float* Ws[4] = {Wf, Wi, Wg, Wo};
    const float* Bs[4] = {bf, bi, bg, bo};

    // ---- setup: stage x into scratch (snapshot region) ----
    float* scratch = (float*)&S->sRmS[0][0][0];   // 8192 B >= 2048 floats
    for (int i = lane; i < TT * DD; i += NTH)
        scratch[i] = inputs[((size_t)(i / DD) * BB + b) * DD + (i % DD)];

    if (lane < 20) {
        int l = lane / 10, w = lane % 10;
        float tz = qparams[(l*10 + w)*3 + 0];
        float tx = qparams[(l*10 + w)*3 + 1];
        float ty = qparams[(l*10 + w)*3 + 2];
        float c1, s1, c2, s2, c3, s3;
        __sincosf(0.5f*tz, &s1, &c1);
        __sincosf(0.5f*tx, &s2, &c2);
        __sincosf(0.5f*ty, &s3, &c3);
        float aAx =  c2*c1, aAy = -c2*s1;   // RX*RZ
        float bAx = -s2*s1, bAy = -s2*c1;
        float ax = c3*aAx - s3*bAx, ay = c3*aAy - s3*bAy;   // U = RY*RX*RZ
        float bx = s3*aAx + c3*bAx, by = s3*aAy + c3*bAy;
        if (l == 0) {
            S->sU0[w] = make_float4(ax, ay, bx, by);
        } else {
            float n00 = ax*ax + ay*ay - bx*bx - by*by;
            float pr  = ax*bx - ay*by;
            float pi_ = ax*by + ay*bx;
            S->sN[w][0] = make_float2( n00, 0.f);
            S->sN[w][1] = make_float2(-2.f*pr,  2.f*pi_);
            S->sN[w][2] = make_float2(-2.f*pr, -2.f*pi_);
            S->sN[w][3] = make_float2(-n00, 0.f);
        }
    }
    __syncwarp();

    // K column-major (needs sN[0])
    if (lane < 16) {
        int cc = lane >> 2, r = lane & 3;
        int idx = ((((cc >> 1) ^ (r >> 1)) << 1) | ((cc & 1) ^ (r & 1)));
        S->sKc[cc * 4 + r] = S->sN[0][idx];
    }
    // sWh
    for (int p = lane; p < 40; p += NTH) {
        const int g = p / 10, h = p % 10;
        const float* Wrow = Ws[g] + h * 42 + DD;
#pragma unroll
        for (int j = 0; j < HH; ++j)
            S->sWh[g][h][j] = 0.5f * Wrow[j];
    }
    __syncwarp();

    // sWx: 0.5*(W.x + b) for all steps
    for (int p = lane; p < 40; p += NTH) {
        const int g = p / 10, h = p % 10;
        const float* Wrow = Ws[g] + h * 42;
        const float bias = Bs[g][h];
        float4 wv[8];
#pragma unroll
        for (int j = 0; j < 8; ++j)
            wv[j] = make_float4(Wrow[4*j], Wrow[4*j+1], Wrow[4*j+2], Wrow[4*j+3]);
        for (int t = 0; t < TT; ++t) {
            const float4* xv = (const float4*)(scratch + t * DD);
            float a0 = 0.f, a1 = 0.f, a2 = 0.f, a3 = 0.f;
#pragma unroll
            for (int j = 0; j < 8; ++j) {
                float4 x4 = xv[j];
                a0 = fmaf(wv[j].x, x4.x, a0);
                a1 = fmaf(wv[j].y, x4.y, a1);
                a2 = fmaf(wv[j].z, x4.z, a2);
                a3 = fmaf(wv[j].w, x4.w, a3);
            }
            S->sWx[t][p] = 0.5f * (((a0 + a1) + (a2 + a3)) + bias);
        }
    }

    const float msk1 = (side == 0) ? 1.f : 0.f;
    float cx_reg = 0.f, hx_reg = 0.f;
    __syncwarp();

    for (int t = 0; t < TT; ++t) {
        // ---- broadcast h, compute 40 preacts -> g tables (2 rounds) ----
        float hj[HH];
#pragma unroll
        for (int j = 0; j < HH; ++j)
            hj[j] = __shfl_sync(0xffffffffu, hx_reg, j);
#pragma unroll
        for (int rr = 0; rr < 2; ++rr) {
            const int p = lane + rr * 32;
            if (p < 40) {
                const int pc = p / 10, pw = p % 10;
                float acc0 = S->sWx[t][p], acc1 = 0.f;
                const float* wh = S->sWh[pc][pw];
#pragma unroll
                for (int j = 0; j < HH; j += 2) {
                    acc0 = fmaf(wh[j],   hj[j],   acc0);
                    acc1 = fmaf(wh[j+1], hj[j+1], acc1);
                }
                float cc, ss;
                __sincosf(acc0 + acc1, &ss, &cc);
                float4 U = S->sU0[pw];
                float2 v0 = make_float2(U.x*cc - U.z*ss, U.y*cc + U.w*ss);
                float2 v1 = make_float2(U.z*cc + U.x*ss, U.w*cc - U.y*ss);
                S->sG[pc][pw][0] = cmulc(v0, v0);
                S->sG[pc][pw][1] = cmulc(v0, v1);
                S->sG[pc][pw][2] = cmulc(v1, v0);
                S->sG[pc][pw][3] = cmulc(v1, v1);
            }
        }
        __syncwarp();

        // ---- column-local chains (no shuffles) ----
        float2 X0, X1, X2, X3;
        if (side == 0) {
            // special first link: Rm_1[r] = N_1[r] * g_1[r^c] * g_0[c]
            float2 d = S->sG[c][0][colIdx];
            const float2* g1 = S->sG[c][1];
            const float2* n1 = S->sN[1];
            X0 = cmul(n1[0], cmul(g1[0 ^ colIdx], d));
            X1 = cmul(n1[1], cmul(g1[1 ^ colIdx], d));
            X2 = cmul(n1[2], cmul(g1[2 ^ colIdx], d));
            X3 = cmul(n1[3], cmul(g1[3 ^ colIdx], d));
            float4* dst = &S->sRmS[c][0][colIdx * 2];
            dst[0] = make_float4(X0.x, X0.y, X1.x, X1.y);
            dst[1] = make_float4(X2.x, X2.y, X3.x, X3.y);
        } else {
            const float2* kc = &S->sKc[colIdx * 4];
            X0 = kc[0]; X1 = kc[1]; X2 = kc[2]; X3 = kc[3];
        }
#pragma unroll
        for (int i = 0; i < 8; ++i) {
            const int j = side ? (9 - i) : (i + 2);
            const float2* gj = S->sG[c][j];
            float2 g0 = gj[0], g1 = gj[1], g2 = gj[2], g3 = gj[3];
            float2 o0 = X0, o3 = X3;
            float2 o1 = make_float2(X1.x * msk1, X1.y * msk1);
            float2 o2 = make_float2(X2.x * msk1, X2.y * msk1);
            float2 a0 = cfma(g0, o0, cfma(g1, o1, cfma(g2, o2, cmul(g3, o3))));
            float2 a1 = cfma(g1, o0, cfma(g0, o1, cfma(g3, o2, cmul(g2, o3))));
            float2 a2 = cfma(g2, o0, cfma(g3, o1, cfma(g0, o2, cmul(g1, o3))));
            float2 a3 = cfma(g3, o0, cfma(g2, o1, cfma(g1, o2, cmul(g0, o3))));
            if (side == 0) {
                const float2* nj = S->sN[j];
                X0 = cmul(nj[0], a0); X1 = cmul(nj[1], a1);
                X2 = cmul(nj[2], a2); X3 = cmul(nj[3], a3);
            } else {
                X0 = a0; X1 = a1; X2 = a2; X3 = a3;
            }
            if (side || i < 7) {
                const int sw = side ? (7 - i) : (i + 1);
                float4* dst = side ? &S->sLS[c][sw][colIdx * 2]
                                   : &S->sRmS[c][sw][colIdx * 2];
                dst[0] = make_float4(X0.x, X0.y, X1.x, X1.y);
                dst[1] = make_float4(X2.x, X2.y, X3.x, X3.y);
            }
        }

        // ---- E_9 / E_0 from live Rm_9 registers (side 0) ----
        {
            float e9 = 0.f, e0 = 0.f;
            if (side == 0) {
                const float2* kc = &S->sKc[colIdx * 4];
                e9 = (kc[0].x*X0.x - kc[0].y*X0.y)
                   + (kc[1].x*X1.x - kc[1].y*X1.y)
                   + (kc[2].x*X2.x - kc[2].y*X2.y)
                   + (kc[3].x*X3.x - kc[3].y*X3.y);
                float2 Xa = (colIdx & 1) ? ((colIdx & 2) ? X3 : X1)
                                         : ((colIdx & 2) ? X2 : X0);
                float2 Xb = (colIdx & 1) ? ((colIdx & 2) ? X0 : X2)
                                         : ((colIdx & 2) ? X1 : X3);
                e0 = Xa.x + Xb.x;
            }
            e9 += __shfl_xor_sync(0xffffffffu, e9, 1);
            e9 += __shfl_xor_sync(0xffffffffu, e9, 2);
            e0 += __shfl_xor_sync(0xffffffffu, e0, 1);
            e0 += __shfl_xor_sync(0xffffffffu, e0, 2);
            if (sub == 0) {
                S->qpart[c][9] = e9;
                S->qpart[c][0] = e0;
            }
        }
        __syncwarp();

        // ---- combine: E_w = Re sum L_w .* Rm_w  (w = 1..8) ----
#pragma unroll
        for (int k = 0; k < 4; ++k) {
            const int w = k + 1 + side * 4;
            const float4* rp = &S->sRmS[c][w - 1][colIdx * 2];
            const float4* lp = &S->sLS[c][w - 1][colIdx * 2];
            float4 ra = rp[0], rb = rp[1];
            float4 la = lp[0], lb = lp[1];
            float e = (la.x*ra.x - la.y*ra.y) + (la.z*ra.z - la.w*ra.w)
                    + (lb.x*rb.x - lb.y*rb.y) + (lb.z*rb.z - lb.w*rb.w);
            e += __shfl_xor_sync(0xffffffffu, e, 1);
            e += __shfl_xor_sync(0xffffffffu, e, 2);
            if (colIdx == 0)
                S->qpart[c][w] = e;
        }
        __syncwarp();

        // ---- LSTM cell update (lanes 0-9) ----
        if (lane < HH) {
            const int h = lane;
            float qf = S->qpart[0][h];
            float qi = S->qpart[1][h];
            float qg = S->qpart[2][h];
            float qo = S->qpart[3][h];
            float fg = fast_sigmoid(qf);
            float ig = fast_sigmoid(qi);
            float gg = fast_tanh(qg);
            float og = fast_sigmoid(qo);
            cx_reg = fg * cx_reg + ig * gg;
            hx_reg = og * fast_tanh(cx_reg);
            out[((size_t)(t*BB) + b)*HH + h] = hx_reg;
        }
        __syncwarp();
    }

    if (lane < HH) {
        out[(size_t)TT*BB*HH + (size_t)b*HH + lane]                 = hx_reg;
        out[(size_t)TT*BB*HH + (size_t)BB*HH + (size_t)b*HH + lane] = cx_reg;
    }
}

extern "C" void kernel_launch(void* const* d_in, const int* in_sizes, int n_in,
                              void* d_out, int out_size) {
    (void)in_sizes; (void)n_in; (void)out_size;
    const float* inputs  = (const float*)d_in[0];
    const float* qparams = (const float*)d_in[1];
    const float* Wf = (const float*)d_in[2];
    const float* bf = (const float*)d_in[3];
    const float* Wi = (const float*)d_in[4];
    const float* bi = (const float*)d_in[5];
    const float* Wg = (const float*)d_in[6];
    const float* bg = (const float*)d_in[7];
    const float* Wo = (const float*)d_in[8];
    const float* bo = (const float*)d_in[9];
    float* out = (float*)d_out;
    cudaFuncSetAttribute(qlstm_kernel,
                         cudaFuncAttributeMaxDynamicSharedMemorySize,
                         (int)sizeof(Smem));
    qlstm_kernel<<<BB, NTH, sizeof(Smem)>>>(inputs, qparams, Wf, bf, Wi, bi,
                                            Wg, bg, Wo, bo, out);
}

// round 16
// speedup vs baseline: 1.3068x; 1.3068x over previous
#include <cuda_runtime.h>

// QLSTM on GB300 — R16: R14's 4-warp/element transfer-matrix layout
// (best measured issue efficiency) + R15's slot cuts:
//   - g tables precomputed in smem by preact lanes (no per-lane cmulc)
//   - fused first Rm link (wires 0+1 in init): 8 chain links, not 9
//   - E_0 / E_9 from live Rm_9 registers
// Chains: Rm (masked prefix, lanes 0-15) and K-contracted L (lanes 16-31),
// unified loop, one warp per circuit.

#define TT 64
#define BB 256
#define DD 32
#define HH 10
#define NTH 128

struct Smem {
    float2 sRm[4][10][16];      // Rm snapshots w=1..8 (+ setup scratch)
    float2 sL[4][10][16];       // L snapshots w=1..8, [9]=K (+ setup scratch)
    float2 sG[4][HH][4];        // per-circuit per-wire g tables (step-dep)
    float2 sN[HH][4];           // N_j = U_j^dag Z U_j (fixed)
    float2 sK[16];              // boundary kernel
    float4 sU0[HH];             // layer-1 gate (ax,ay,bx,by)
    float  sWx[TT][40];         // 0.5*(W.x + b) all steps
    float  sWh[4][HH][HH];      // 0.5*W_h
    float  qpart[2][4][HH];
};

__device__ __forceinline__ float2 cmul(float2 a, float2 b) {
    return make_float2(a.x*b.x - a.y*b.y, a.x*b.y + a.y*b.x);
}
__device__ __forceinline__ float2 cmulc(float2 a, float2 b) {   // conj(a)*b
    return make_float2(a.x*b.x + a.y*b.y, a.x*b.y - a.y*b.x);
}
__device__ __forceinline__ float2 cfma(float2 a, float2 b, float2 acc) {
    acc.x = fmaf(a.x, b.x, fmaf(-a.y, b.y, acc.x));
    acc.y = fmaf(a.x, b.y, fmaf( a.y, b.x, acc.y));
    return acc;
}
__device__ __forceinline__ float fast_tanh(float x) {
    float r;
    asm("tanh.approx.f32 %0, %1;" : "=f"(r) : "f"(x));
    return r;
}
__device__ __forceinline__ float fast_sigmoid(float x) {
    return fmaf(0.5f, fast_tanh(0.5f * x), 0.5f);
}

__global__ void __launch_bounds__(NTH, 2)
qlstm_kernel(const float* __restrict__ inputs,
             const float* __restrict__ qparams,
             const float* __restrict__ Wf, const float* __restrict__ bf,
             const float* __restrict__ Wi, const float* __restrict__ bi,
             const float* __restrict__ Wg, const float* __restrict__ bg,
             const float* __restrict__ Wo, const float* __restrict__ bo,
             float* __restrict__ out)
{
    extern __shared__ char smem_raw[];
    Smem* S = (Smem*)smem_raw;

    const int tid  = threadIdx.x;
    const int b    = blockIdx.x;
    const int c    = tid >> 5;        // circuit == warp
    const int lane = tid & 31;
    const int half = lane >> 4;       // 0: Rm chain, 1: L chain
    const int ln   = lane & 15;
    const int row  = ln >> 2;
    const int col  = ln & 3;

    const float* Ws[4] = {Wf, Wi, Wg, Wo};
    const float* Bs[4] = {bf, bi, bg, bo};

    // ---- setup phase 1: stage x into scratch (sRm+sL region), gate consts --
    float* scratch = (float*)&S->sRm[0][0][0];   // 2560 float2 >= 2048 floats
    for (int i = tid; i < TT * DD; i += NTH)
        scratch[i] = inputs[((size_t)(i / DD) * BB + b) * DD + (i % DD)];

    if (tid < 20) {
        int l = tid / 10, w = tid % 10;
        float tz = qparams[(l*10 + w)*3 + 0];
        float tx = qparams[(l*10 + w)*3 + 1];
        float ty = qparams[(l*10 + w)*3 + 2];
        float c1, s1, c2, s2, c3, s3;
        __sincosf(0.5f*tz, &s1, &c1);
        __sincosf(0.5f*tx, &s2, &c2);
        __sincosf(0.5f*ty, &s3, &c3);
        float aAx =  c2*c1, aAy = -c2*s1;   // RX*RZ
        float bAx = -s2*s1, bAy = -s2*c1;
        float ax = c3*aAx - s3*bAx, ay = c3*aAy - s3*bAy;   // U = RY*RX*RZ
        float bx = s3*aAx + c3*bAx, by = s3*aAy + c3*bAy;
        if (l == 0) {
            S->sU0[w] = make_float4(ax, ay, bx, by);
        } else {
            float n00 = ax*ax + ay*ay - bx*bx - by*by;
            float pr  = ax*bx - ay*by;
            float pi_ = ax*by + ay*bx;
            S->sN[w][0] = make_float2( n00, 0.f);
            S->sN[w][1] = make_float2(-2.f*pr,  2.f*pi_);
            S->sN[w][2] = make_float2(-2.f*pr, -2.f*pi_);
            S->sN[w][3] = make_float2(-n00, 0.f);
        }
    }
    __syncthreads();

    // ---- setup phase 2: 0.5*(W.x + b); W_h; K ----
    if (tid < 120) {
        const int trio = tid / 40, pr = tid % 40;
        const int g = pr / 10, h = pr % 10;
        const float* Wrow = Ws[g] + h * 42;
        const float bias = Bs[g][h];
        float wreg[DD];
#pragma unroll
        for (int j = 0; j < DD; ++j) wreg[j] = Wrow[j];
        const int t0 = (trio == 0) ? 0 : (trio == 1) ? 22 : 44;
        const int t1 = (trio == 0) ? 22 : (trio == 1) ? 44 : TT;
        for (int t = t0; t < t1; ++t) {
            const float* xv = scratch + t * DD;
            float a0 = 0.f, a1 = 0.f, a2 = 0.f, a3 = 0.f;
#pragma unroll
            for (int j = 0; j < DD; j += 4) {
                a0 = fmaf(wreg[j],   xv[j],   a0);
                a1 = fmaf(wreg[j+1], xv[j+1], a1);
                a2 = fmaf(wreg[j+2], xv[j+2], a2);
                a3 = fmaf(wreg[j+3], xv[j+3], a3);
            }
            S->sWx[t][pr] = 0.5f * (((a0 + a1) + (a2 + a3)) + bias);
        }
    }
    if (tid < 40) {
        const int g = tid / 10, h = tid % 10;
        const float* Wrow = Ws[g] + h * 42 + DD;
#pragma unroll
        for (int j = 0; j < HH; ++j)
            S->sWh[g][h][j] = 0.5f * Wrow[j];
    }
    if (tid < 16) {
        int r = tid >> 2, cc = tid & 3;
        int idx = (((cc >> 1) ^ (r >> 1)) << 1) | ((cc & 1) ^ (r & 1));
        S->sK[tid] = S->sN[0][idx];
    }
    __syncthreads();

    // ---- setup phase 3: L_9 = K (after scratch consumed) ----
    if (tid < 64) {
        int cc = tid >> 4, e = tid & 15;
        S->sL[cc][9][e] = S->sK[e];
    }

    // ---- per-lane chain constants ----
    int gk[4], srck[4];
    float cmk[4];
    if (half == 0) {
#pragma unroll
        for (int k = 0; k < 4; ++k) {
            gk[k] = row ^ k;
            srck[k] = k * 4 + col;
            cmk[k] = 1.f;
        }
    } else {
        gk[0] = row;     srck[0] = 16 + col;      cmk[0] = 1.f;
        gk[1] = row ^ 3; srck[1] = 16 + 12 + col; cmk[1] = 1.f;
        gk[2] = 0; srck[2] = lane; cmk[2] = 0.f;
        gk[3] = 0; srck[3] = lane; cmk[3] = 0.f;
    }
    const bool e0_mask = (half == 0) && ((col == row) || (col == (row ^ 3)));

    float cx_reg = 0.f, hx_reg = 0.f;
    __syncthreads();

    for (int t = 0; t < TT; ++t) {
        const int par = t & 1;

        // ---- pre-activation (h-part) -> g tables (lanes 0-9) ----
        float hj[HH];
#pragma unroll
        for (int j = 0; j < HH; ++j)
            hj[j] = __shfl_sync(0xffffffffu, hx_reg, j);
        if (lane < HH) {
            float acc0 = S->sWx[t][c * 10 + lane], acc1 = 0.f;
            const float* wh = S->sWh[c][lane];
#pragma unroll
            for (int j = 0; j < HH; j += 2) {
                acc0 = fmaf(wh[j],   hj[j],   acc0);
                acc1 = fmaf(wh[j+1], hj[j+1], acc1);
            }
            float cc, ss;
            __sincosf(acc0 + acc1, &ss, &cc);
            float4 U = S->sU0[lane];
            float2 v0 = make_float2(U.x*cc - U.z*ss, U.y*cc + U.w*ss);
            float2 v1 = make_float2(U.z*cc + U.x*ss, U.w*cc - U.y*ss);
            S->sG[c][lane][0] = cmulc(v0, v0);
            S->sG[c][lane][1] = cmulc(v0, v1);
            S->sG[c][lane][2] = cmulc(v1, v0);
            S->sG[c][lane][3] = cmulc(v1, v1);
        }
        __syncwarp();

        // ---- chains: Rm forward (lanes 0-15), L backward (lanes 16-31) ----
        float2 R;
        if (half == 0) {
            // fused init: Rm_1[r,c] = N_1[r] * g_1[r^c] * g_0[c]
            float2 d   = S->sG[c][0][col];
            float2 g1v = S->sG[c][1][row ^ col];
            R = cmul(S->sN[1][row], cmul(g1v, d));
            S->sRm[c][1][ln] = R;
        } else {
            R = S->sK[ln];                        // L_9 = K
        }
#pragma unroll
        for (int i = 0; i < 8; ++i) {
            const int j = half ? (9 - i) : (i + 2);
            const float2* gj = S->sG[c][j];
            float2 cf[4];
#pragma unroll
            for (int k = 0; k < 4; ++k) {
                float2 gv = gj[gk[k]];
                cf[k] = make_float2(gv.x * cmk[k], gv.y * cmk[k]);
            }
            float2 old[4];
#pragma unroll
            for (int k = 0; k < 4; ++k) {
                old[k].x = __shfl_sync(0xffffffffu, R.x, srck[k]);
                old[k].y = __shfl_sync(0xffffffffu, R.y, srck[k]);
            }
            float2 acc = make_float2(0.f, 0.f);
#pragma unroll
            for (int k = 0; k < 4; ++k)
                acc = cfma(cf[k], old[k], acc);
            if (half == 0) {
                R = cmul(S->sN[j][row], acc);
                if (i < 7) S->sRm[c][i + 2][ln] = R;   // Rm_9 stays live
            } else {
                R = acc;
                S->sL[c][8 - i][ln] = R;               // L_8 .. L_1
            }
        }

        // ---- E_0: masked register reduce over live Rm_9 ----
        {
            float e0 = e0_mask ? R.x : 0.f;
            e0 += __shfl_xor_sync(0xffffffffu, e0, 1);
            e0 += __shfl_xor_sync(0xffffffffu, e0, 2);
            e0 += __shfl_xor_sync(0xffffffffu, e0, 4);
            e0 += __shfl_xor_sync(0xffffffffu, e0, 8);
            if (lane == 0)
                S->qpart[par][c][0] = e0;
        }
        __syncwarp();

        // ---- combine: E_w = Re sum_ln L_w[ln] * Rm_w[ln] ----
#pragma unroll
        for (int p = 0; p < 5; ++p) {
            const int w = 1 + 2*p + half;
            float e = 0.f;
            if (w <= 9) {
                float2 L  = S->sL[c][w][ln];
                float2 rm = (p == 4) ? R : S->sRm[c][w][ln];  // w=9: live reg
                e = fmaf(L.x, rm.x, -L.y * rm.y);
            }
            e += __shfl_xor_sync(0xffffffffu, e, 1);
            e += __shfl_xor_sync(0xffffffffu, e, 2);
            e += __shfl_xor_sync(0xffffffffu, e, 4);
            e += __shfl_xor_sync(0xffffffffu, e, 8);
            if (ln == 0 && w <= 9)
                S->qpart[par][c][w] = e;
        }
        __syncthreads();

        // ---- LSTM cell update (lanes 0-9 of every warp, redundant) ----
        if (lane < HH) {
            const int h = lane;
            float qf = S->qpart[par][0][h];
            float qi = S->qpart[par][1][h];
            float qg = S->qpart[par][2][h];
            float qo = S->qpart[par][3][h];
            float fg = fast_sigmoid(qf);
            float ig = fast_sigmoid(qi);
            float gg = fast_tanh(qg);
            float og = fast_sigmoid(qo);
            cx_reg = fg * cx_reg + ig * gg;
            hx_reg = og * fast_tanh(cx_reg);
            if (c == 0)
                out[((size_t)(t*BB) + b)*HH + h] = hx_reg;
        }
        __syncwarp();
    }

    if (c == 0 && lane < HH) {
        out[(size_t)TT*BB*HH + (size_t)b*HH + lane]                 = hx_reg;
        out[(size_t)TT*BB*HH + (size_t)BB*HH + (size_t)b*HH + lane] = cx_reg;
    }
}

extern "C" void kernel_launch(void* const* d_in, const int* in_sizes, int n_in,
                              void* d_out, int out_size) {
    (void)in_sizes; (void)n_in; (void)out_size;
    const float* inputs  = (const float*)d_in[0];
    const float* qparams = (const float*)d_in[1];
    const float* Wf = (const float*)d_in[2];
    const float* bf = (const float*)d_in[3];
    const float* Wi = (const float*)d_in[4];
    const float* bi = (const float*)d_in[5];
    const float* Wg = (const float*)d_in[6];
    const float* bg = (const float*)d_in[7];
    const float* Wo = (const float*)d_in[8];
    const float* bo = (const float*)d_in[9];
    float* out = (float*)d_out;
    cudaFuncSetAttribute(qlstm_kernel,
                         cudaFuncAttributeMaxDynamicSharedMemorySize,
                         (int)sizeof(Smem));
    qlstm_kernel<<<BB, NTH, sizeof(Smem)>>>(inputs, qparams, Wf, bf, Wi, bi,
                                            Wg, bg, Wo, bo, out);
}